// round 8
// baseline (speedup 1.0000x reference)
#include <cuda_runtime.h>
#include <math.h>
#include <stdint.h>

#define NB   16
#define NS   1024
#define ND   512
#define NT   3
#define NBT  48

__device__ float g_Q [(size_t)NBT * NS * ND];   // Q (tf32 vals); reused as attended
__device__ float g_K [(size_t)NBT * NS * ND];   // K (tf32 vals)
__device__ float g_V [(size_t)NBT * NS * ND];   // V (tf32 vals)
__device__ float g_Sc[(size_t)NBT * NS * NS];   // scores / probs(tf32 vals)
__device__ float g_F [(size_t)NT * NB * NS * ND];  // rounded features
__device__ float g_W [(size_t)NT * ND * ND];       // rounded Wq,Wk,Wv

// ---------------------------------------------------------------------------
// tf32 warp-MMA GEMM v4: CTA tile 128(M) x 256(N), BK=32, 256 threads,
// 8 warps (2x4), warp tile 64x64, cp.async 3-STAGE pipeline, 1 barrier/iter.
// Operands in GMEM are ALREADY tf32-rounded -> raw-bit cp.async is lossless.
// BLAY=0: B is [N x K] row-major (K contig)  -> C = A * B^T
// BLAY=1: B is [K x N] row-major (N contig)  -> C = A * B
// ---------------------------------------------------------------------------
#define ASTR 36         // A/B(K-major) row stride words: (36g+tig)%32 = 4g+tig
#define BSTR 264        // B(N-major) row stride words: (264k+n)%32 -> 8tig+g
#define A_WORDS 4608    // 128*36
#define B_WORDS 9216    // 256*36 (>= 32*264=8448)
#define STAGE   13824   // A_WORDS + B_WORDS
#define NSTAGE  3
#define SMEM_WORDS (NSTAGE*STAGE)   // 41472 words = 165888 B

constexpr int BM = 128, BN = 256, BK = 32;

__device__ __forceinline__ uint32_t f2tf32(float x) {
    uint32_t r; asm("cvt.rna.tf32.f32 %0, %1;" : "=r"(r) : "f"(x)); return r;
}
__device__ __forceinline__ float rna(float x) { return __uint_as_float(f2tf32(x)); }

__device__ __forceinline__ uint32_t smem_u32(const void* p) {
    uint32_t a;
    asm("{ .reg .u64 t; cvta.to.shared.u64 t, %1; cvt.u32.u64 %0, t; }" : "=r"(a) : "l"(p));
    return a;
}
__device__ __forceinline__ void cp16(uint32_t saddr, const void* g) {
    asm volatile("cp.async.cg.shared.global [%0], [%1], 16;" :: "r"(saddr), "l"(g));
}
__device__ __forceinline__ void mma_tf32(float c[4], const uint32_t a[4], const uint32_t b[2]) {
    asm volatile(
        "mma.sync.aligned.m16n8k8.row.col.f32.tf32.tf32.f32 "
        "{%0,%1,%2,%3}, {%4,%5,%6,%7}, {%8,%9}, {%0,%1,%2,%3};"
        : "+f"(c[0]), "+f"(c[1]), "+f"(c[2]), "+f"(c[3])
        : "r"(a[0]), "r"(a[1]), "r"(a[2]), "r"(a[3]), "r"(b[0]), "r"(b[1]));
}

template<int BLAY, bool BIAS, bool SCALE, bool ROUND>
__device__ __forceinline__ void gemm_tf32(
    const float* __restrict__ A, int lda,
    const float* __restrict__ Bm, int ldb,
    const float* __restrict__ bias, float alpha,
    float* __restrict__ C, int ldc, int K, int n0)
{
    extern __shared__ uint32_t sh[];
    const uint32_t sbase = smem_u32(sh);

    const int tid  = threadIdx.x;
    const int lane = tid & 31;
    const int wid  = tid >> 5;
    const int g    = lane >> 2;
    const int tig  = lane & 3;
    const int wm   = (wid & 1) * 64;
    const int wn   = (wid >> 1) * 64;

    float acc[4][8][4];
#pragma unroll
    for (int i = 0; i < 4; i++)
#pragma unroll
        for (int j = 0; j < 8; j++)
#pragma unroll
            for (int q = 0; q < 4; q++) acc[i][j][q] = 0.f;

    auto issue = [&](int buf, int k0) {
        const uint32_t a0 = sbase + (uint32_t)(buf * STAGE) * 4u;
        const uint32_t b0 = a0 + (uint32_t)A_WORDS * 4u;
#pragma unroll
        for (int i = 0; i < 4; i++) {              // A: 1024 x 16B chunks
            const int c = tid + 256 * i, row = c >> 3, q = c & 7;
            cp16(a0 + (uint32_t)(row * ASTR + q * 4) * 4u,
                 A + (size_t)row * lda + k0 + q * 4);
        }
        if (BLAY == 0) {
#pragma unroll
            for (int i = 0; i < 8; i++) {          // B: 256 rows x 8 chunks
                const int c = tid + 256 * i, row = c >> 3, q = c & 7;
                cp16(b0 + (uint32_t)(row * ASTR + q * 4) * 4u,
                     Bm + (size_t)(n0 + row) * ldb + k0 + q * 4);
            }
        } else {
#pragma unroll
            for (int i = 0; i < 8; i++) {          // B: 32 rows x 64 chunks
                const int c = tid + 256 * i, row = c >> 6, q = c & 63;
                cp16(b0 + (uint32_t)(row * BSTR + q * 4) * 4u,
                     Bm + (size_t)(k0 + row) * ldb + n0 + q * 4);
            }
        }
        asm volatile("cp.async.commit_group;" ::: "memory");
    };

    // 3-stage pipeline, ONE __syncthreads per iteration.
    issue(0, 0);
    issue(1, BK);

    const int niter = K / BK;
    int buf = 0;
    for (int it = 0; it < niter; it++) {
        // groups committed: 0..it+1; need group `it` done -> <=1 outstanding
        asm volatile("cp.async.wait_group 1;" ::: "memory");
        __syncthreads();   // all warps see stage `it`; all done with compute(it-1)

        // stage it+2 goes into buffer (it+2)%3 == (it-1)%3, free as of this sync
        if (it + 2 < niter) {
            int nb = buf + 2; if (nb >= NSTAGE) nb -= NSTAGE;
            issue(nb, (it + 2) * BK);
        } else {
            asm volatile("cp.async.commit_group;" ::: "memory");  // keep group count in step
        }

        const uint32_t* As = &sh[buf * STAGE];
        const uint32_t* Bs = As + A_WORDS;
#pragma unroll
        for (int kk = 0; kk < BK; kk += 8) {
            uint32_t af[4][4], bf[8][2];
#pragma unroll
            for (int mt = 0; mt < 4; mt++) {
                const int row = wm + mt * 16 + g;
                af[mt][0] = As[row * ASTR + kk + tig];
                af[mt][1] = As[(row + 8) * ASTR + kk + tig];
                af[mt][2] = As[row * ASTR + kk + tig + 4];
                af[mt][3] = As[(row + 8) * ASTR + kk + tig + 4];
            }
#pragma unroll
            for (int nt = 0; nt < 8; nt++) {
                const int n = wn + nt * 8 + g;
                if (BLAY == 0) {
                    bf[nt][0] = Bs[n * ASTR + kk + tig];
                    bf[nt][1] = Bs[n * ASTR + kk + tig + 4];
                } else {
                    bf[nt][0] = Bs[(kk + tig) * BSTR + n];
                    bf[nt][1] = Bs[(kk + tig + 4) * BSTR + n];
                }
            }
#pragma unroll
            for (int mt = 0; mt < 4; mt++)
#pragma unroll
                for (int nt = 0; nt < 8; nt++)
                    mma_tf32(acc[mt][nt], af[mt], bf[nt]);
        }
        if (++buf == NSTAGE) buf = 0;
    }

    // epilogue
#pragma unroll
    for (int nt = 0; nt < 8; nt++) {
        const int col = n0 + wn + nt * 8 + tig * 2;
        float b0 = 0.f, b1 = 0.f;
        if (BIAS) { b0 = bias[col]; b1 = bias[col + 1]; }
#pragma unroll
        for (int mt = 0; mt < 4; mt++) {
            const int row = wm + mt * 16 + g;
            float v0 = acc[mt][nt][0], v1 = acc[mt][nt][1];
            float v2 = acc[mt][nt][2], v3 = acc[mt][nt][3];
            if (SCALE) { v0 *= alpha; v1 *= alpha; v2 *= alpha; v3 *= alpha; }
            if (BIAS)  { v0 += b0; v1 += b1; v2 += b0; v3 += b1; }
            if (ROUND) { v0 = rna(v0); v1 = rna(v1); v2 = rna(v2); v3 = rna(v3); }
            *(float2*)(C + (size_t)row * ldc + col)       = make_float2(v0, v1);
            *(float2*)(C + (size_t)(row + 8) * ldc + col) = make_float2(v2, v3);
        }
    }
}

// ---------------------------------------------------------------------------
// pre-pass: RNA-round tensors into g_F / g_W
// ---------------------------------------------------------------------------
__global__ __launch_bounds__(256)
void k_round(const float4* __restrict__ src, int which, int n4)
{
    int idx = blockIdx.x * 256 + threadIdx.x;
    if (idx >= n4) return;
    float4* dst = (which < 3)
        ? (float4*)(g_F + (size_t)which * (NB * NS * ND))
        : (float4*)(g_W + (size_t)(which - 3) * (ND * ND));
    float4 v = src[idx];
    v.x = rna(v.x); v.y = rna(v.y); v.z = rna(v.z); v.w = rna(v.w);
    dst[idx] = v;
}

// ---------------------------------------------------------------------------
__global__ __launch_bounds__(256, 1)
void k_qkv(const float* __restrict__ bq, const float* __restrict__ bk,
           const float* __restrict__ bv)
{
    const int mt = blockIdx.y;
    const int bt = mt >> 3;
    const int b = bt / NT, t = bt - b * NT;
    const float* A = g_F + (size_t)t * (NB * NS * ND)
                         + ((size_t)b * NS + (size_t)(mt & 7) * BM) * ND;
    const float* W = g_W + (size_t)blockIdx.z * (ND * ND);

    const float* bias; float* Cbuf;
    if (blockIdx.z == 0)      { bias = bq; Cbuf = g_Q; }
    else if (blockIdx.z == 1) { bias = bk; Cbuf = g_K; }
    else                      { bias = bv; Cbuf = g_V; }

    float* C = Cbuf + (size_t)mt * BM * ND;
    gemm_tf32<0, true, false, true>(A, ND, W, ND, bias, 1.f, C, ND, ND,
                                    blockIdx.x * BN);
}

__global__ __launch_bounds__(256, 1)
void k_scores()
{
    const int mt = blockIdx.y;
    const int bt = mt >> 3;
    const float* A  = g_Q + (size_t)mt * BM * ND;
    const float* Bp = g_K + (size_t)bt * NS * ND;
    float* C = g_Sc + (size_t)mt * BM * NS;
    gemm_tf32<0, false, true, false>(A, ND, Bp, ND, nullptr,
                                     0.044194173824159216f, C, NS, ND,
                                     blockIdx.x * BN);
}

__global__ __launch_bounds__(256, 1)
void k_pv()
{
    const int mt = blockIdx.y;
    const int bt = mt >> 3;
    const float* A  = g_Sc + (size_t)mt * BM * NS;   // probs (tf32 vals)
    const float* Bp = g_V + (size_t)bt * NS * ND;    // V [K x N] (tf32 vals)
    float* C = g_Q + (size_t)mt * BM * ND;
    gemm_tf32<1, false, false, false>(A, NS, Bp, ND, nullptr, 1.f, C, ND, NS,
                                      blockIdx.x * BN);
}

// ---------------------------------------------------------------------------
__global__ __launch_bounds__(256)
void k_softmax()
{
    const int row  = blockIdx.x * 8 + (threadIdx.x >> 5);
    const int lane = threadIdx.x & 31;
    float4* p = (float4*)(g_Sc + (size_t)row * NS);

    float4 v[8];
    float m = -1e30f;
#pragma unroll
    for (int i = 0; i < 8; i++) {
        v[i] = p[lane + 32 * i];
        m = fmaxf(m, fmaxf(fmaxf(v[i].x, v[i].y), fmaxf(v[i].z, v[i].w)));
    }
#pragma unroll
    for (int off = 16; off >= 1; off >>= 1)
        m = fmaxf(m, __shfl_xor_sync(0xffffffffu, m, off));

    float s = 0.f;
#pragma unroll
    for (int i = 0; i < 8; i++) {
        v[i].x = __expf(v[i].x - m); v[i].y = __expf(v[i].y - m);
        v[i].z = __expf(v[i].z - m); v[i].w = __expf(v[i].w - m);
        s += v[i].x + v[i].y + v[i].z + v[i].w;
    }
#pragma unroll
    for (int off = 16; off >= 1; off >>= 1)
        s += __shfl_xor_sync(0xffffffffu, s, off);

    const float inv = 1.0f / s;
#pragma unroll
    for (int i = 0; i < 8; i++) {
        v[i].x = rna(v[i].x * inv); v[i].y = rna(v[i].y * inv);
        v[i].z = rna(v[i].z * inv); v[i].w = rna(v[i].w * inv);
        p[lane + 32 * i] = v[i];
    }
}

__global__ __launch_bounds__(256)
void k_combine(const float* __restrict__ tfw, float* __restrict__ out)
{
    float w0 = tfw[0], w1 = tfw[1], w2 = tfw[2];
    float mx = fmaxf(w0, fmaxf(w1, w2));
    float e0 = __expf(w0 - mx), e1 = __expf(w1 - mx), e2 = __expf(w2 - mx);
    float inv = 1.0f / (e0 + e1 + e2);
    w0 = e0 * inv; w1 = e1 * inv; w2 = e2 * inv;

    const size_t per_b = (size_t)NS * ND / 4;
    size_t idx = (size_t)blockIdx.x * blockDim.x + threadIdx.x;
    const size_t n4 = (size_t)NB * per_b;
    if (idx >= n4) return;
    size_t b = idx / per_b;
    size_t r = idx % per_b;

    const float4* A = (const float4*)g_Q;
    float4 x0 = A[(b * 3 + 0) * per_b + r];
    float4 x1 = A[(b * 3 + 1) * per_b + r];
    float4 x2 = A[(b * 3 + 2) * per_b + r];
    float4 o;
    o.x = w0 * x0.x + w1 * x1.x + w2 * x2.x;
    o.y = w0 * x0.y + w1 * x1.y + w2 * x2.y;
    o.z = w0 * x0.z + w1 * x1.z + w2 * x2.z;
    o.w = w0 * x0.w + w1 * x1.w + w2 * x2.w;
    ((float4*)out)[idx] = o;
}

// ---------------------------------------------------------------------------
extern "C" void kernel_launch(void* const* d_in, const int* in_sizes, int n_in,
                              void* d_out, int out_size)
{
    (void)in_sizes; (void)n_in; (void)out_size;
    const float* f4h = (const float*)d_in[0];
    const float* f1d = (const float*)d_in[1];
    const float* f1w = (const float*)d_in[2];
    const float* Wq  = (const float*)d_in[3];
    const float* bq  = (const float*)d_in[4];
    const float* Wk  = (const float*)d_in[5];
    const float* bk  = (const float*)d_in[6];
    const float* Wv  = (const float*)d_in[7];
    const float* bv  = (const float*)d_in[8];
    const float* tfw = (const float*)d_in[9];
    float* out = (float*)d_out;

    const int smem_bytes = SMEM_WORDS * 4;   // 165888
    cudaFuncSetAttribute(k_qkv,    cudaFuncAttributeMaxDynamicSharedMemorySize, smem_bytes);
    cudaFuncSetAttribute(k_scores, cudaFuncAttributeMaxDynamicSharedMemorySize, smem_bytes);
    cudaFuncSetAttribute(k_pv,     cudaFuncAttributeMaxDynamicSharedMemorySize, smem_bytes);

    const int nf4 = NB * NS * ND / 4;    // 2,097,152
    const int nw4 = ND * ND / 4;         // 65,536

    dim3 blk(256);
    k_round<<<nf4 / 256, blk>>>((const float4*)f4h, 0, nf4);
    k_round<<<nf4 / 256, blk>>>((const float4*)f1d, 1, nf4);
    k_round<<<nf4 / 256, blk>>>((const float4*)f1w, 2, nf4);
    k_round<<<nw4 / 256, blk>>>((const float4*)Wq, 3, nw4);
    k_round<<<nw4 / 256, blk>>>((const float4*)Wk, 4, nw4);
    k_round<<<nw4 / 256, blk>>>((const float4*)Wv, 5, nw4);

    k_qkv    <<<dim3(ND/BN, (NBT*NS)/BM, 3), blk, smem_bytes>>>(bq, bk, bv);
    k_scores <<<dim3(NS/BN, (NBT*NS)/BM),    blk, smem_bytes>>>();
    k_softmax<<<(NBT*NS)/8,                  blk>>>();
    k_pv     <<<dim3(ND/BN, (NBT*NS)/BM),    blk, smem_bytes>>>();
    k_combine<<<(NB*NS*ND/4 + 255)/256,      blk>>>(tfw, out);
}